// round 14
// baseline (speedup 1.0000x reference)
#include <cuda_runtime.h>
#include <cstdint>

#define N_NODES 100000
#define N_EDGES 3200000
#define IN_DIM  500
#define HID     16
#define OUT_DIM 500

#define SCAN_NODES 1024
#define NB_SCAN ((N_NODES + SCAN_NODES - 1) / SCAN_NODES)   // 98
#define NBINS 512

typedef unsigned long long ull;

// ---------------- scratch (device globals: no cudaMalloc allowed) ----------
__device__ float g_dis  [N_NODES];
__device__ float g_t    [N_NODES * HID];
__device__ float g_a    [N_NODES * HID];
__device__ int   g_cnt  [N_NODES];
__device__ int   g_scan [N_NODES];
__device__ int   g_bsum [NB_SCAN];
__device__ int   g_boff [NB_SCAN];
__device__ int   g_off  [N_NODES];
__device__ int   g_cur  [N_NODES];
__device__ int   g_csrc [N_EDGES];
__device__ int   g_hist [NBINS];       // degree histogram
__device__ int   g_hcur [NBINS];       // bin cursors
__device__ int   g_order[N_NODES];     // nodes sorted by degree

// ---------------- f32x2 packed helpers --------------------------------------
__device__ __forceinline__ void fma2(ull& d, ull a, ull b) {
    asm("fma.rn.f32x2 %0, %1, %2, %0;" : "+l"(d) : "l"(a), "l"(b));
}
__device__ __forceinline__ ull pack2(float f) {
    ull r; unsigned u = __float_as_uint(f);
    asm("mov.b64 %0, {%1, %1};" : "=l"(r) : "r"(u));
    return r;
}
__device__ __forceinline__ ull pack2(float lo, float hi) {
    ull r;
    asm("mov.b64 %0, {%1, %2};" : "=l"(r) : "r"(__float_as_uint(lo)), "r"(__float_as_uint(hi)));
    return r;
}
__device__ __forceinline__ float2 unpack2(ull v) {
    unsigned a, b;
    asm("mov.b64 {%0, %1}, %2;" : "=r"(a), "=r"(b) : "l"(v));
    return make_float2(__uint_as_float(a), __uint_as_float(b));
}

// ---------------- CSR build --------------------------------------------------
__global__ void k_reset_cnt() {
    int i = blockIdx.x * blockDim.x + threadIdx.x;
    if (i < N_NODES) g_cnt[i] = 0;
    if (i < NBINS)   g_hist[i] = 0;
}

__global__ void k_count(const int* __restrict__ dst) {
    int e = blockIdx.x * blockDim.x + threadIdx.x;
    if (e < N_EDGES) atomicAdd(&g_cnt[dst[e]], 1);
}

__global__ void __launch_bounds__(256) k_scan1() {
    __shared__ int sm[256];
    int tid  = threadIdx.x;
    int base = blockIdx.x * SCAN_NODES + tid * 4;
    int c0 = 0, c1 = 0, c2 = 0, c3 = 0;
    if (base + 0 < N_NODES) c0 = g_cnt[base + 0];
    if (base + 1 < N_NODES) c1 = g_cnt[base + 1];
    if (base + 2 < N_NODES) c2 = g_cnt[base + 2];
    if (base + 3 < N_NODES) c3 = g_cnt[base + 3];
    if (base + 0 < N_NODES) g_dis[base + 0] = rsqrtf((float)c0 + 1.0f);
    if (base + 1 < N_NODES) g_dis[base + 1] = rsqrtf((float)c1 + 1.0f);
    if (base + 2 < N_NODES) g_dis[base + 2] = rsqrtf((float)c2 + 1.0f);
    if (base + 3 < N_NODES) g_dis[base + 3] = rsqrtf((float)c3 + 1.0f);
    int tsum = c0 + c1 + c2 + c3;
    sm[tid] = tsum;
    __syncthreads();
    #pragma unroll
    for (int d = 1; d < 256; d <<= 1) {
        int v = (tid >= d) ? sm[tid - d] : 0;
        __syncthreads();
        sm[tid] += v;
        __syncthreads();
    }
    int excl = sm[tid] - tsum;
    if (base + 0 < N_NODES) g_scan[base + 0] = excl;
    if (base + 1 < N_NODES) g_scan[base + 1] = excl + c0;
    if (base + 2 < N_NODES) g_scan[base + 2] = excl + c0 + c1;
    if (base + 3 < N_NODES) g_scan[base + 3] = excl + c0 + c1 + c2;
    if (tid == 255) g_bsum[blockIdx.x] = sm[255];
}

__global__ void __launch_bounds__(128) k_scan2() {
    __shared__ int sm[128];
    int tid = threadIdx.x;
    int v0 = (tid < NB_SCAN) ? g_bsum[tid] : 0;
    sm[tid] = v0;
    __syncthreads();
    #pragma unroll
    for (int d = 1; d < 128; d <<= 1) {
        int v = (tid >= d) ? sm[tid - d] : 0;
        __syncthreads();
        sm[tid] += v;
        __syncthreads();
    }
    if (tid < NB_SCAN) g_boff[tid] = sm[tid] - v0;
}

__global__ void k_scan3() {
    int n = blockIdx.x * blockDim.x + threadIdx.x;
    if (n >= N_NODES) return;
    int o = g_scan[n] + g_boff[n >> 10];
    g_off[n] = o;
    g_cur[n] = o;
}

__global__ void k_fill(const int* __restrict__ src, const int* __restrict__ dst) {
    int e = blockIdx.x * blockDim.x + threadIdx.x;
    if (e >= N_EDGES) return;
    int d = dst[e];
    int pos = atomicAdd(&g_cur[d], 1);
    g_csrc[pos] = src[e];
}

// ---------------- degree counting sort ---------------------------------------
__global__ void k_hist() {
    int n = blockIdx.x * blockDim.x + threadIdx.x;
    if (n >= N_NODES) return;
    int b = g_cnt[n]; if (b > NBINS - 1) b = NBINS - 1;
    atomicAdd(&g_hist[b], 1);
}

__global__ void __launch_bounds__(NBINS) k_hscan() {
    __shared__ int sm[NBINS];
    int tid = threadIdx.x;
    int v0 = g_hist[tid];
    sm[tid] = v0;
    __syncthreads();
    #pragma unroll
    for (int d = 1; d < NBINS; d <<= 1) {
        int v = (tid >= d) ? sm[tid - d] : 0;
        __syncthreads();
        sm[tid] += v;
        __syncthreads();
    }
    g_hcur[tid] = sm[tid] - v0;      // exclusive offsets = initial cursors
}

__global__ void k_horder() {
    int n = blockIdx.x * blockDim.x + threadIdx.x;
    if (n >= N_NODES) return;
    int b = g_cnt[n]; if (b > NBINS - 1) b = NBINS - 1;
    int pos = atomicAdd(&g_hcur[b], 1);
    g_order[pos] = n;
}

// ---------------- GEMM1 (unscaled): g_t = X @ W1   [100k,500]x[500,16] -----
#define G1K2(xp, yp, kk) do { \
    const ulonglong2* wr_ = &Ws[(kk) * 4]; \
    ulonglong2 w0_ = wr_[0], w1_ = wr_[1], w2_ = wr_[2], w3_ = wr_[3]; \
    fma2(a0, xp, w0_.x); fma2(a1, xp, w0_.y); \
    fma2(a2, xp, w1_.x); fma2(a3, xp, w1_.y); \
    fma2(a4, xp, w2_.x); fma2(a5, xp, w2_.y); \
    fma2(a6, xp, w3_.x); fma2(a7, xp, w3_.y); \
    fma2(c0, yp, w0_.x); fma2(c1, yp, w0_.y); \
    fma2(c2, yp, w1_.x); fma2(c3, yp, w1_.y); \
    fma2(c4, yp, w2_.x); fma2(c5, yp, w2_.y); \
    fma2(c6, yp, w3_.x); fma2(c7, yp, w3_.y); \
} while (0)

__global__ void __launch_bounds__(256, 2) k_gemm1(const float* __restrict__ x,
                                                  const float* __restrict__ W1) {
    __shared__ ulonglong2 Ws[IN_DIM * 4];        // 32000 B
    __shared__ float part[32][128];              // 16384 B
    const ulonglong2* Wv = (const ulonglong2*)W1;
    for (int i = threadIdx.x; i < IN_DIM * 4; i += 256) Ws[i] = Wv[i];
    __syncthreads();

    int rp   = threadIdx.x & 127;
    int half = threadIdx.x >> 7;
    int row0 = blockIdx.x * 256 + rp * 2;
    bool valid = row0 < N_NODES;

    ull a0=0,a1=0,a2=0,a3=0,a4=0,a5=0,a6=0,a7=0;
    ull c0=0,c1=0,c2=0,c3=0,c4=0,c5=0,c6=0,c7=0;

    if (valid) {
        const float4* xr0 = (const float4*)(x + (long)row0 * IN_DIM);
        const float4* xr1 = (const float4*)(x + (long)(row0 + 1) * IN_DIM);
        int k4  = half ? 63 : 0;
        int end = half ? 125 : 63;
        while (k4 < end) {
            float4 ba[4], bb[4];
            int m = end - k4; if (m > 4) m = 4;
            #pragma unroll
            for (int i = 0; i < 4; i++)
                if (i < m) { ba[i] = xr0[k4 + i]; bb[i] = xr1[k4 + i]; }
            #pragma unroll
            for (int i = 0; i < 4; i++) {
                if (i < m) {
                    int kb = (k4 + i) * 4;
                    G1K2(pack2(ba[i].x), pack2(bb[i].x), kb + 0);
                    G1K2(pack2(ba[i].y), pack2(bb[i].y), kb + 1);
                    G1K2(pack2(ba[i].z), pack2(bb[i].z), kb + 2);
                    G1K2(pack2(ba[i].w), pack2(bb[i].w), kb + 3);
                }
            }
            k4 += 4;
        }
    }

    if (half && valid) {
        float2 f;
        f = unpack2(a0); part[0][rp]  = f.x; part[1][rp]  = f.y;
        f = unpack2(a1); part[2][rp]  = f.x; part[3][rp]  = f.y;
        f = unpack2(a2); part[4][rp]  = f.x; part[5][rp]  = f.y;
        f = unpack2(a3); part[6][rp]  = f.x; part[7][rp]  = f.y;
        f = unpack2(a4); part[8][rp]  = f.x; part[9][rp]  = f.y;
        f = unpack2(a5); part[10][rp] = f.x; part[11][rp] = f.y;
        f = unpack2(a6); part[12][rp] = f.x; part[13][rp] = f.y;
        f = unpack2(a7); part[14][rp] = f.x; part[15][rp] = f.y;
        f = unpack2(c0); part[16][rp] = f.x; part[17][rp] = f.y;
        f = unpack2(c1); part[18][rp] = f.x; part[19][rp] = f.y;
        f = unpack2(c2); part[20][rp] = f.x; part[21][rp] = f.y;
        f = unpack2(c3); part[22][rp] = f.x; part[23][rp] = f.y;
        f = unpack2(c4); part[24][rp] = f.x; part[25][rp] = f.y;
        f = unpack2(c5); part[26][rp] = f.x; part[27][rp] = f.y;
        f = unpack2(c6); part[28][rp] = f.x; part[29][rp] = f.y;
        f = unpack2(c7); part[30][rp] = f.x; part[31][rp] = f.y;
    }
    __syncthreads();
    if (!half && valid) {
        float o[16]; float2 f;
        f = unpack2(a0); o[0]  = f.x + part[0][rp];  o[1]  = f.y + part[1][rp];
        f = unpack2(a1); o[2]  = f.x + part[2][rp];  o[3]  = f.y + part[3][rp];
        f = unpack2(a2); o[4]  = f.x + part[4][rp];  o[5]  = f.y + part[5][rp];
        f = unpack2(a3); o[6]  = f.x + part[6][rp];  o[7]  = f.y + part[7][rp];
        f = unpack2(a4); o[8]  = f.x + part[8][rp];  o[9]  = f.y + part[9][rp];
        f = unpack2(a5); o[10] = f.x + part[10][rp]; o[11] = f.y + part[11][rp];
        f = unpack2(a6); o[12] = f.x + part[12][rp]; o[13] = f.y + part[13][rp];
        f = unpack2(a7); o[14] = f.x + part[14][rp]; o[15] = f.y + part[15][rp];
        float4* tr0 = (float4*)(g_t + (long)row0 * HID);
        tr0[0] = make_float4(o[0],  o[1],  o[2],  o[3]);
        tr0[1] = make_float4(o[4],  o[5],  o[6],  o[7]);
        tr0[2] = make_float4(o[8],  o[9],  o[10], o[11]);
        tr0[3] = make_float4(o[12], o[13], o[14], o[15]);
        f = unpack2(c0); o[0]  = f.x + part[16][rp]; o[1]  = f.y + part[17][rp];
        f = unpack2(c1); o[2]  = f.x + part[18][rp]; o[3]  = f.y + part[19][rp];
        f = unpack2(c2); o[4]  = f.x + part[20][rp]; o[5]  = f.y + part[21][rp];
        f = unpack2(c3); o[6]  = f.x + part[22][rp]; o[7]  = f.y + part[23][rp];
        f = unpack2(c4); o[8]  = f.x + part[24][rp]; o[9]  = f.y + part[25][rp];
        f = unpack2(c5); o[10] = f.x + part[26][rp]; o[11] = f.y + part[27][rp];
        f = unpack2(c6); o[12] = f.x + part[28][rp]; o[13] = f.y + part[29][rp];
        f = unpack2(c7); o[14] = f.x + part[30][rp]; o[15] = f.y + part[31][rp];
        float4* tr1 = (float4*)(g_t + (long)(row0 + 1) * HID);
        tr1[0] = make_float4(o[0],  o[1],  o[2],  o[3]);
        tr1[1] = make_float4(o[4],  o[5],  o[6],  o[7]);
        tr1[2] = make_float4(o[8],  o[9],  o[10], o[11]);
        tr1[3] = make_float4(o[12], o[13], o[14], o[15]);
    }
}

// ---------------- join point: g_t *= dis[row] --------------------------------
__global__ void k_scale() {
    int t = blockIdx.x * blockDim.x + threadIdx.x;
    if (t >= N_NODES * 4) return;
    int n = t >> 2;
    float s = g_dis[n];
    float4 v = ((const float4*)g_t)[t];
    v.x *= s; v.y *= s; v.z *= s; v.w *= s;
    ((float4*)g_t)[t] = v;
}

// ---------------- fused CSR-gather aggregation + layer epilogue --------------
// Nodes processed in degree-sorted order (g_order) -> warp-homogeneous loops.
// MODE 0: src g_t -> relu(s*(acc+self)+b1) @ W2 * s -> g_a
// MODE 1: src g_a -> relu(s*(acc+self)+b2) * s       -> g_t
// MODE 2: src g_t -> s*(acc+self)                    -> g_a
template<int MODE>
__global__ void __launch_bounds__(256) k_agg_fused(const float* __restrict__ bias,
                                                   const float* __restrict__ W2) {
    __shared__ float4 Ws4[64];
    __shared__ float4 bs4[4];
    if (MODE == 0) {
        if (threadIdx.x < 64) Ws4[threadIdx.x] = ((const float4*)W2)[threadIdx.x];
        if (threadIdx.x < 4)  bs4[threadIdx.x] = ((const float4*)bias)[threadIdx.x];
        __syncthreads();
    } else if (MODE == 1) {
        if (threadIdx.x < 4)  bs4[threadIdx.x] = ((const float4*)bias)[threadIdx.x];
        __syncthreads();
    }

    int t = blockIdx.x * 256 + threadIdx.x;
    int p = t >> 2;
    bool valid = p < N_NODES;
    int pp = valid ? p : (N_NODES - 1);
    int nn = g_order[pp];                 // degree-sorted node id
    int q = t & 3;

    const float* srcbuf = (MODE == 1) ? g_a : g_t;
    float*       dstbuf = (MODE == 1) ? g_t : g_a;

    int off = g_off[nn];
    int cnt = g_cnt[nn];
    float s = g_dis[nn];
    const int* cs = g_csrc + off;

    float4 acc = make_float4(0.f, 0.f, 0.f, 0.f);
    int i = 0;
    for (; i + 8 <= cnt; i += 8) {
        int s0 = __ldg(cs + i + 0);
        int s1 = __ldg(cs + i + 1);
        int s2 = __ldg(cs + i + 2);
        int s3 = __ldg(cs + i + 3);
        int s4 = __ldg(cs + i + 4);
        int s5 = __ldg(cs + i + 5);
        int s6 = __ldg(cs + i + 6);
        int s7 = __ldg(cs + i + 7);
        float4 v0 = __ldg((const float4*)(srcbuf + (long)s0 * HID) + q);
        float4 v1 = __ldg((const float4*)(srcbuf + (long)s1 * HID) + q);
        float4 v2 = __ldg((const float4*)(srcbuf + (long)s2 * HID) + q);
        float4 v3 = __ldg((const float4*)(srcbuf + (long)s3 * HID) + q);
        float4 v4 = __ldg((const float4*)(srcbuf + (long)s4 * HID) + q);
        float4 v5 = __ldg((const float4*)(srcbuf + (long)s5 * HID) + q);
        float4 v6 = __ldg((const float4*)(srcbuf + (long)s6 * HID) + q);
        float4 v7 = __ldg((const float4*)(srcbuf + (long)s7 * HID) + q);
        acc.x += ((v0.x + v1.x) + (v2.x + v3.x)) + ((v4.x + v5.x) + (v6.x + v7.x));
        acc.y += ((v0.y + v1.y) + (v2.y + v3.y)) + ((v4.y + v5.y) + (v6.y + v7.y));
        acc.z += ((v0.z + v1.z) + (v2.z + v3.z)) + ((v4.z + v5.z) + (v6.z + v7.z));
        acc.w += ((v0.w + v1.w) + (v2.w + v3.w)) + ((v4.w + v5.w) + (v6.w + v7.w));
    }
    for (; i + 4 <= cnt; i += 4) {
        int s0 = __ldg(cs + i + 0);
        int s1 = __ldg(cs + i + 1);
        int s2 = __ldg(cs + i + 2);
        int s3 = __ldg(cs + i + 3);
        float4 v0 = __ldg((const float4*)(srcbuf + (long)s0 * HID) + q);
        float4 v1 = __ldg((const float4*)(srcbuf + (long)s1 * HID) + q);
        float4 v2 = __ldg((const float4*)(srcbuf + (long)s2 * HID) + q);
        float4 v3 = __ldg((const float4*)(srcbuf + (long)s3 * HID) + q);
        acc.x += (v0.x + v1.x) + (v2.x + v3.x);
        acc.y += (v0.y + v1.y) + (v2.y + v3.y);
        acc.z += (v0.z + v1.z) + (v2.z + v3.z);
        acc.w += (v0.w + v1.w) + (v2.w + v3.w);
    }
    for (; i < cnt; i++) {
        int s0 = __ldg(cs + i);
        float4 v0 = __ldg((const float4*)(srcbuf + (long)s0 * HID) + q);
        acc.x += v0.x; acc.y += v0.y; acc.z += v0.z; acc.w += v0.w;
    }
    float4 self = __ldg((const float4*)(srcbuf + (long)nn * HID) + q);

    float4 pre;
    pre.x = s * (acc.x + self.x);
    pre.y = s * (acc.y + self.y);
    pre.z = s * (acc.z + self.z);
    pre.w = s * (acc.w + self.w);

    float4 outv;
    if (MODE == 0 || MODE == 1) {
        float4 b = bs4[q];
        pre.x = fmaxf(pre.x + b.x, 0.f);
        pre.y = fmaxf(pre.y + b.y, 0.f);
        pre.z = fmaxf(pre.z + b.z, 0.f);
        pre.w = fmaxf(pre.w + b.w, 0.f);
    }
    if (MODE == 0) {
        int lane = threadIdx.x & 31;
        int base = lane & ~3;
        float4 y = make_float4(0.f, 0.f, 0.f, 0.f);
        #pragma unroll
        for (int k = 0; k < HID; k++) {
            float hsrc = (k & 3) == 0 ? pre.x : (k & 3) == 1 ? pre.y
                       : (k & 3) == 2 ? pre.z : pre.w;
            float hk = __shfl_sync(0xffffffffu, hsrc, base | (k >> 2));
            float4 wk = Ws4[k * 4 + q];
            y.x = fmaf(hk, wk.x, y.x);
            y.y = fmaf(hk, wk.y, y.y);
            y.z = fmaf(hk, wk.z, y.z);
            y.w = fmaf(hk, wk.w, y.w);
        }
        outv = make_float4(y.x * s, y.y * s, y.z * s, y.w * s);
    } else if (MODE == 1) {
        outv = make_float4(pre.x * s, pre.y * s, pre.z * s, pre.w * s);
    } else {
        outv = pre;
    }
    if (valid) ((float4*)(dstbuf + (long)nn * HID))[q] = outv;
}

// ---- GEMM3: out = g_a @ W3 + b3  [100k,16]x[16,500] ------------------------
__global__ void __launch_bounds__(128) k_gemm3(const float* __restrict__ W3,
                                               const float* __restrict__ b3,
                                               float* __restrict__ out) {
    __shared__ float4 as4[64 * 4];
    int tid = threadIdx.x;
    int r0  = blockIdx.x * 64;
    int nrows = N_NODES - r0; if (nrows > 64) nrows = 64;

    const float4* av = (const float4*)(g_a + (long)r0 * HID);
    for (int i = tid; i < nrows * 4; i += 128) as4[i] = av[i];
    __syncthreads();

    if (tid >= 125) return;
    int c = tid * 4;

    ull w[32];
    #pragma unroll
    for (int k = 0; k < HID; k++) {
        float4 wv = *(const float4*)(W3 + k * OUT_DIM + c);
        w[k*2+0] = pack2(wv.x, wv.y);
        w[k*2+1] = pack2(wv.z, wv.w);
    }
    float4 bb = *(const float4*)(b3 + c);
    ull b01 = pack2(bb.x, bb.y), b23 = pack2(bb.z, bb.w);

    for (int r = 0; r < nrows; r++) {
        ull acc0 = b01, acc1 = b23;
        #pragma unroll
        for (int k4 = 0; k4 < 4; k4++) {
            float4 a = as4[r * 4 + k4];
            int kb = k4 * 4;
            { ull ap = pack2(a.x); fma2(acc0, ap, w[(kb+0)*2]); fma2(acc1, ap, w[(kb+0)*2+1]); }
            { ull ap = pack2(a.y); fma2(acc0, ap, w[(kb+1)*2]); fma2(acc1, ap, w[(kb+1)*2+1]); }
            { ull ap = pack2(a.z); fma2(acc0, ap, w[(kb+2)*2]); fma2(acc1, ap, w[(kb+2)*2+1]); }
            { ull ap = pack2(a.w); fma2(acc0, ap, w[(kb+3)*2]); fma2(acc1, ap, w[(kb+3)*2+1]); }
        }
        float2 lo = unpack2(acc0), hi = unpack2(acc1);
        *(float4*)(out + (long)(r0 + r) * OUT_DIM + c) = make_float4(lo.x, lo.y, hi.x, hi.y);
    }
}

// ---------------- launch ----------------------------------------------------
extern "C" void kernel_launch(void* const* d_in, const int* in_sizes, int n_in,
                              void* d_out, int out_size) {
    const float* x   = (const float*)d_in[0];
    const int*   ei  = (const int*)  d_in[1];
    const float* W1  = (const float*)d_in[2];
    const float* b1  = (const float*)d_in[3];
    const float* W2  = (const float*)d_in[4];
    const float* b2  = (const float*)d_in[5];
    const float* W3  = (const float*)d_in[6];
    const float* b3  = (const float*)d_in[7];
    float* out = (float*)d_out;

    const int* src = ei;
    const int* dst = ei + N_EDGES;

    static cudaStream_t s2 = 0;
    static cudaEvent_t evF = 0, evJ = 0;
    static int init_ok = -1;
    if (init_ok < 0) {
        init_ok = 1;
        if (cudaStreamCreateWithFlags(&s2, cudaStreamNonBlocking) != cudaSuccess) init_ok = 0;
        if (init_ok && cudaEventCreateWithFlags(&evF, cudaEventDisableTiming) != cudaSuccess) init_ok = 0;
        if (init_ok && cudaEventCreateWithFlags(&evJ, cudaEventDisableTiming) != cudaSuccess) init_ok = 0;
    }

    const int TB = 256;
    const int gN   = (N_NODES + TB - 1) / TB;              // 391
    const int gE   = (N_EDGES + TB - 1) / TB;              // 12500
    const int gG1  = (N_NODES + 255) / 256;                // 391
    const int gA   = (N_NODES * 4 + TB - 1) / TB;          // 1563
    const int g64  = (N_NODES + 63) / 64;                  // 1563

    cudaStream_t sb = init_ok ? s2 : (cudaStream_t)0;

    if (init_ok) {
        cudaEventRecord(evF, 0);
        cudaStreamWaitEvent(s2, evF, 0);
    }

    // Branch B: CSR build + normalization + degree counting sort (hidden under gemm1)
    k_reset_cnt<<<gN, TB, 0, sb>>>();
    k_count<<<gE, TB, 0, sb>>>(dst);
    k_scan1<<<NB_SCAN, 256, 0, sb>>>();
    k_scan2<<<1, 128, 0, sb>>>();
    k_scan3<<<gN, TB, 0, sb>>>();
    k_fill<<<gE, TB, 0, sb>>>(src, dst);
    k_hist<<<gN, TB, 0, sb>>>();
    k_hscan<<<1, NBINS, 0, sb>>>();
    k_horder<<<gN, TB, 0, sb>>>();

    // Branch A: dense layer-1 GEMM (unscaled)
    k_gemm1<<<gG1, TB>>>(x, W1);

    if (init_ok) {
        cudaEventRecord(evJ, s2);
        cudaStreamWaitEvent(0, evJ, 0);
    }

    // join: scale layer-1 features
    k_scale<<<gA, TB>>>();

    // layer 1 -> 2: agg + relu+b1 + @W2 + scale   (g_t -> g_a)
    k_agg_fused<0><<<gA, TB>>>(b1, W2);
    // layer 2 -> 3: agg + relu+b2 + scale          (g_a -> g_t)
    k_agg_fused<1><<<gA, TB>>>(b2, nullptr);
    // layer 3: agg + final scale                   (g_t -> g_a)
    k_agg_fused<2><<<gA, TB>>>(nullptr, nullptr);
    // up-projection
    k_gemm3<<<g64, 128>>>(W3, b3, out);
}

// round 15
// speedup vs baseline: 1.1602x; 1.1602x over previous
#include <cuda_runtime.h>
#include <cstdint>

#define N_NODES 100000
#define N_EDGES 3200000
#define IN_DIM  500
#define HID     16
#define OUT_DIM 500

#define SCAN_NODES 1024
#define NB_SCAN ((N_NODES + SCAN_NODES - 1) / SCAN_NODES)   // 98

// ---------------- scratch (device globals: no cudaMalloc allowed) ----------
__device__ float g_dis [N_NODES];
__device__ float g_t   [N_NODES * HID];
__device__ float g_a   [N_NODES * HID];
__device__ int   g_cnt [N_NODES];
__device__ int   g_scan[N_NODES];
__device__ int   g_bsum[NB_SCAN];
__device__ int   g_boff[NB_SCAN];
__device__ int   g_off [N_NODES];
__device__ int   g_cur [N_NODES];
__device__ int   g_csrc[N_EDGES];

// ---------------- f32x2 packed helpers --------------------------------------
__device__ __forceinline__ void fma2(unsigned long long& d,
                                     unsigned long long a, unsigned long long b) {
    asm("fma.rn.f32x2 %0, %1, %2, %0;" : "+l"(d) : "l"(a), "l"(b));
}
__device__ __forceinline__ unsigned long long pack2(float f) {
    unsigned long long r; unsigned u = __float_as_uint(f);
    asm("mov.b64 %0, {%1, %1};" : "=l"(r) : "r"(u));
    return r;
}
__device__ __forceinline__ unsigned long long pack2(float lo, float hi) {
    unsigned long long r;
    asm("mov.b64 %0, {%1, %2};" : "=l"(r) : "r"(__float_as_uint(lo)), "r"(__float_as_uint(hi)));
    return r;
}
__device__ __forceinline__ float2 unpack2(unsigned long long v) {
    unsigned a, b;
    asm("mov.b64 {%0, %1}, %2;" : "=r"(a), "=r"(b) : "l"(v));
    return make_float2(__uint_as_float(a), __uint_as_float(b));
}

// ---------------- CSR build --------------------------------------------------
__global__ void k_reset_cnt() {
    int i = blockIdx.x * blockDim.x + threadIdx.x;
    if (i < N_NODES) g_cnt[i] = 0;
}

__global__ void k_count(const int* __restrict__ dst) {
    int e = blockIdx.x * blockDim.x + threadIdx.x;
    if (e < N_EDGES) atomicAdd(&g_cnt[dst[e]], 1);
}

__global__ void __launch_bounds__(256) k_scan1() {
    __shared__ int sm[256];
    int tid  = threadIdx.x;
    int base = blockIdx.x * SCAN_NODES + tid * 4;
    int c0 = 0, c1 = 0, c2 = 0, c3 = 0;
    if (base + 0 < N_NODES) c0 = g_cnt[base + 0];
    if (base + 1 < N_NODES) c1 = g_cnt[base + 1];
    if (base + 2 < N_NODES) c2 = g_cnt[base + 2];
    if (base + 3 < N_NODES) c3 = g_cnt[base + 3];
    if (base + 0 < N_NODES) g_dis[base + 0] = rsqrtf((float)c0 + 1.0f);
    if (base + 1 < N_NODES) g_dis[base + 1] = rsqrtf((float)c1 + 1.0f);
    if (base + 2 < N_NODES) g_dis[base + 2] = rsqrtf((float)c2 + 1.0f);
    if (base + 3 < N_NODES) g_dis[base + 3] = rsqrtf((float)c3 + 1.0f);
    int tsum = c0 + c1 + c2 + c3;
    sm[tid] = tsum;
    __syncthreads();
    #pragma unroll
    for (int d = 1; d < 256; d <<= 1) {
        int v = (tid >= d) ? sm[tid - d] : 0;
        __syncthreads();
        sm[tid] += v;
        __syncthreads();
    }
    int excl = sm[tid] - tsum;
    if (base + 0 < N_NODES) g_scan[base + 0] = excl;
    if (base + 1 < N_NODES) g_scan[base + 1] = excl + c0;
    if (base + 2 < N_NODES) g_scan[base + 2] = excl + c0 + c1;
    if (base + 3 < N_NODES) g_scan[base + 3] = excl + c0 + c1 + c2;
    if (tid == 255) g_bsum[blockIdx.x] = sm[255];
}

__global__ void __launch_bounds__(128) k_scan2() {
    __shared__ int sm[128];
    int tid = threadIdx.x;
    int v0 = (tid < NB_SCAN) ? g_bsum[tid] : 0;
    sm[tid] = v0;
    __syncthreads();
    #pragma unroll
    for (int d = 1; d < 128; d <<= 1) {
        int v = (tid >= d) ? sm[tid - d] : 0;
        __syncthreads();
        sm[tid] += v;
        __syncthreads();
    }
    if (tid < NB_SCAN) g_boff[tid] = sm[tid] - v0;
}

__global__ void k_scan3() {
    int n = blockIdx.x * blockDim.x + threadIdx.x;
    if (n >= N_NODES) return;
    int o = g_scan[n] + g_boff[n >> 10];
    g_off[n] = o;
    g_cur[n] = o;
}

__global__ void k_fill(const int* __restrict__ src, const int* __restrict__ dst) {
    int e = blockIdx.x * blockDim.x + threadIdx.x;
    if (e >= N_EDGES) return;
    int d = dst[e];
    int pos = atomicAdd(&g_cur[d], 1);
    g_csrc[pos] = src[e];
}

// ---------------- GEMM1 (unscaled): g_t = X @ W1   [100k,500]x[500,16] -----
#define G1K2(xp, yp, kk) do { \
    const ulonglong2* wr_ = &Ws[(kk) * 4]; \
    ulonglong2 w0_ = wr_[0], w1_ = wr_[1], w2_ = wr_[2], w3_ = wr_[3]; \
    fma2(a0, xp, w0_.x); fma2(a1, xp, w0_.y); \
    fma2(a2, xp, w1_.x); fma2(a3, xp, w1_.y); \
    fma2(a4, xp, w2_.x); fma2(a5, xp, w2_.y); \
    fma2(a6, xp, w3_.x); fma2(a7, xp, w3_.y); \
    fma2(c0, yp, w0_.x); fma2(c1, yp, w0_.y); \
    fma2(c2, yp, w1_.x); fma2(c3, yp, w1_.y); \
    fma2(c4, yp, w2_.x); fma2(c5, yp, w2_.y); \
    fma2(c6, yp, w3_.x); fma2(c7, yp, w3_.y); \
} while (0)

__global__ void __launch_bounds__(256, 2) k_gemm1(const float* __restrict__ x,
                                                  const float* __restrict__ W1) {
    __shared__ ulonglong2 Ws[IN_DIM * 4];        // 32000 B
    __shared__ float part[32][128];              // 16384 B
    const ulonglong2* Wv = (const ulonglong2*)W1;
    for (int i = threadIdx.x; i < IN_DIM * 4; i += 256) Ws[i] = Wv[i];
    __syncthreads();

    int rp   = threadIdx.x & 127;
    int half = threadIdx.x >> 7;
    int row0 = blockIdx.x * 256 + rp * 2;
    bool valid = row0 < N_NODES;

    unsigned long long a0=0,a1=0,a2=0,a3=0,a4=0,a5=0,a6=0,a7=0;
    unsigned long long c0=0,c1=0,c2=0,c3=0,c4=0,c5=0,c6=0,c7=0;

    if (valid) {
        const float4* xr0 = (const float4*)(x + (long)row0 * IN_DIM);
        const float4* xr1 = (const float4*)(x + (long)(row0 + 1) * IN_DIM);
        int k4  = half ? 63 : 0;
        int end = half ? 125 : 63;
        while (k4 < end) {
            float4 ba[4], bb[4];
            int m = end - k4; if (m > 4) m = 4;
            #pragma unroll
            for (int i = 0; i < 4; i++)
                if (i < m) { ba[i] = xr0[k4 + i]; bb[i] = xr1[k4 + i]; }
            #pragma unroll
            for (int i = 0; i < 4; i++) {
                if (i < m) {
                    int kb = (k4 + i) * 4;
                    G1K2(pack2(ba[i].x), pack2(bb[i].x), kb + 0);
                    G1K2(pack2(ba[i].y), pack2(bb[i].y), kb + 1);
                    G1K2(pack2(ba[i].z), pack2(bb[i].z), kb + 2);
                    G1K2(pack2(ba[i].w), pack2(bb[i].w), kb + 3);
                }
            }
            k4 += 4;
        }
    }

    if (half && valid) {
        float2 f;
        f = unpack2(a0); part[0][rp]  = f.x; part[1][rp]  = f.y;
        f = unpack2(a1); part[2][rp]  = f.x; part[3][rp]  = f.y;
        f = unpack2(a2); part[4][rp]  = f.x; part[5][rp]  = f.y;
        f = unpack2(a3); part[6][rp]  = f.x; part[7][rp]  = f.y;
        f = unpack2(a4); part[8][rp]  = f.x; part[9][rp]  = f.y;
        f = unpack2(a5); part[10][rp] = f.x; part[11][rp] = f.y;
        f = unpack2(a6); part[12][rp] = f.x; part[13][rp] = f.y;
        f = unpack2(a7); part[14][rp] = f.x; part[15][rp] = f.y;
        f = unpack2(c0); part[16][rp] = f.x; part[17][rp] = f.y;
        f = unpack2(c1); part[18][rp] = f.x; part[19][rp] = f.y;
        f = unpack2(c2); part[20][rp] = f.x; part[21][rp] = f.y;
        f = unpack2(c3); part[22][rp] = f.x; part[23][rp] = f.y;
        f = unpack2(c4); part[24][rp] = f.x; part[25][rp] = f.y;
        f = unpack2(c5); part[26][rp] = f.x; part[27][rp] = f.y;
        f = unpack2(c6); part[28][rp] = f.x; part[29][rp] = f.y;
        f = unpack2(c7); part[30][rp] = f.x; part[31][rp] = f.y;
    }
    __syncthreads();
    if (!half && valid) {
        float o[16]; float2 f;
        f = unpack2(a0); o[0]  = f.x + part[0][rp];  o[1]  = f.y + part[1][rp];
        f = unpack2(a1); o[2]  = f.x + part[2][rp];  o[3]  = f.y + part[3][rp];
        f = unpack2(a2); o[4]  = f.x + part[4][rp];  o[5]  = f.y + part[5][rp];
        f = unpack2(a3); o[6]  = f.x + part[6][rp];  o[7]  = f.y + part[7][rp];
        f = unpack2(a4); o[8]  = f.x + part[8][rp];  o[9]  = f.y + part[9][rp];
        f = unpack2(a5); o[10] = f.x + part[10][rp]; o[11] = f.y + part[11][rp];
        f = unpack2(a6); o[12] = f.x + part[12][rp]; o[13] = f.y + part[13][rp];
        f = unpack2(a7); o[14] = f.x + part[14][rp]; o[15] = f.y + part[15][rp];
        float4* tr0 = (float4*)(g_t + (long)row0 * HID);
        tr0[0] = make_float4(o[0],  o[1],  o[2],  o[3]);
        tr0[1] = make_float4(o[4],  o[5],  o[6],  o[7]);
        tr0[2] = make_float4(o[8],  o[9],  o[10], o[11]);
        tr0[3] = make_float4(o[12], o[13], o[14], o[15]);
        f = unpack2(c0); o[0]  = f.x + part[16][rp]; o[1]  = f.y + part[17][rp];
        f = unpack2(c1); o[2]  = f.x + part[18][rp]; o[3]  = f.y + part[19][rp];
        f = unpack2(c2); o[4]  = f.x + part[20][rp]; o[5]  = f.y + part[21][rp];
        f = unpack2(c3); o[6]  = f.x + part[22][rp]; o[7]  = f.y + part[23][rp];
        f = unpack2(c4); o[8]  = f.x + part[24][rp]; o[9]  = f.y + part[25][rp];
        f = unpack2(c5); o[10] = f.x + part[26][rp]; o[11] = f.y + part[27][rp];
        f = unpack2(c6); o[12] = f.x + part[28][rp]; o[13] = f.y + part[29][rp];
        f = unpack2(c7); o[14] = f.x + part[30][rp]; o[15] = f.y + part[31][rp];
        float4* tr1 = (float4*)(g_t + (long)(row0 + 1) * HID);
        tr1[0] = make_float4(o[0],  o[1],  o[2],  o[3]);
        tr1[1] = make_float4(o[4],  o[5],  o[6],  o[7]);
        tr1[2] = make_float4(o[8],  o[9],  o[10], o[11]);
        tr1[3] = make_float4(o[12], o[13], o[14], o[15]);
    }
}

// ---------------- join point: g_t *= dis[row] --------------------------------
__global__ void k_scale() {
    int t = blockIdx.x * blockDim.x + threadIdx.x;
    if (t >= N_NODES * 4) return;
    int n = t >> 2;
    float s = g_dis[n];
    float4 v = ((const float4*)g_t)[t];
    v.x *= s; v.y *= s; v.z *= s; v.w *= s;
    ((float4*)g_t)[t] = v;
}

// ---------------- fused CSR-gather aggregation + layer epilogue --------------
// MODE 0: src g_t -> relu(s*(acc+self)+b1) @ W2 * s -> g_a
// MODE 1: src g_a -> relu(s*(acc+self)+b2) * s       -> g_t
// MODE 2: src g_t -> s*(acc+self)                    -> g_a
template<int MODE>
__global__ void __launch_bounds__(256) k_agg_fused(const float* __restrict__ bias,
                                                   const float* __restrict__ W2) {
    __shared__ float4 Ws4[64];
    __shared__ float4 bs4[4];
    if (MODE == 0) {
        if (threadIdx.x < 64) Ws4[threadIdx.x] = ((const float4*)W2)[threadIdx.x];
        if (threadIdx.x < 4)  bs4[threadIdx.x] = ((const float4*)bias)[threadIdx.x];
        __syncthreads();
    } else if (MODE == 1) {
        if (threadIdx.x < 4)  bs4[threadIdx.x] = ((const float4*)bias)[threadIdx.x];
        __syncthreads();
    }

    int t = blockIdx.x * 256 + threadIdx.x;
    int n = t >> 2;
    bool valid = n < N_NODES;
    int nn = valid ? n : (N_NODES - 1);       // clamp; all lanes stay active for shfl
    int q = t & 3;

    const float* srcbuf = (MODE == 1) ? g_a : g_t;
    float*       dstbuf = (MODE == 1) ? g_t : g_a;

    int off = g_off[nn];
    int cnt = g_cnt[nn];
    const int* cs = g_csrc + off;

    float4 acc = make_float4(0.f, 0.f, 0.f, 0.f);
    int i = 0;
    // 8-deep unroll: 8 independent gathers in flight per lane
    for (; i + 8 <= cnt; i += 8) {
        int s0 = __ldg(cs + i + 0);
        int s1 = __ldg(cs + i + 1);
        int s2 = __ldg(cs + i + 2);
        int s3 = __ldg(cs + i + 3);
        int s4 = __ldg(cs + i + 4);
        int s5 = __ldg(cs + i + 5);
        int s6 = __ldg(cs + i + 6);
        int s7 = __ldg(cs + i + 7);
        float4 v0 = __ldg((const float4*)(srcbuf + (long)s0 * HID) + q);
        float4 v1 = __ldg((const float4*)(srcbuf + (long)s1 * HID) + q);
        float4 v2 = __ldg((const float4*)(srcbuf + (long)s2 * HID) + q);
        float4 v3 = __ldg((const float4*)(srcbuf + (long)s3 * HID) + q);
        float4 v4 = __ldg((const float4*)(srcbuf + (long)s4 * HID) + q);
        float4 v5 = __ldg((const float4*)(srcbuf + (long)s5 * HID) + q);
        float4 v6 = __ldg((const float4*)(srcbuf + (long)s6 * HID) + q);
        float4 v7 = __ldg((const float4*)(srcbuf + (long)s7 * HID) + q);
        acc.x += ((v0.x + v1.x) + (v2.x + v3.x)) + ((v4.x + v5.x) + (v6.x + v7.x));
        acc.y += ((v0.y + v1.y) + (v2.y + v3.y)) + ((v4.y + v5.y) + (v6.y + v7.y));
        acc.z += ((v0.z + v1.z) + (v2.z + v3.z)) + ((v4.z + v5.z) + (v6.z + v7.z));
        acc.w += ((v0.w + v1.w) + (v2.w + v3.w)) + ((v4.w + v5.w) + (v6.w + v7.w));
    }
    for (; i + 4 <= cnt; i += 4) {
        int s0 = __ldg(cs + i + 0);
        int s1 = __ldg(cs + i + 1);
        int s2 = __ldg(cs + i + 2);
        int s3 = __ldg(cs + i + 3);
        float4 v0 = __ldg((const float4*)(srcbuf + (long)s0 * HID) + q);
        float4 v1 = __ldg((const float4*)(srcbuf + (long)s1 * HID) + q);
        float4 v2 = __ldg((const float4*)(srcbuf + (long)s2 * HID) + q);
        float4 v3 = __ldg((const float4*)(srcbuf + (long)s3 * HID) + q);
        acc.x += (v0.x + v1.x) + (v2.x + v3.x);
        acc.y += (v0.y + v1.y) + (v2.y + v3.y);
        acc.z += (v0.z + v1.z) + (v2.z + v3.z);
        acc.w += (v0.w + v1.w) + (v2.w + v3.w);
    }
    for (; i < cnt; i++) {
        int s0 = __ldg(cs + i);
        float4 v0 = __ldg((const float4*)(srcbuf + (long)s0 * HID) + q);
        acc.x += v0.x; acc.y += v0.y; acc.z += v0.z; acc.w += v0.w;
    }
    float4 self = __ldg((const float4*)(srcbuf + (long)nn * HID) + q);
    float s = g_dis[nn];

    float4 pre;
    pre.x = s * (acc.x + self.x);
    pre.y = s * (acc.y + self.y);
    pre.z = s * (acc.z + self.z);
    pre.w = s * (acc.w + self.w);

    float4 outv;
    if (MODE == 0 || MODE == 1) {
        float4 b = bs4[q];
        pre.x = fmaxf(pre.x + b.x, 0.f);
        pre.y = fmaxf(pre.y + b.y, 0.f);
        pre.z = fmaxf(pre.z + b.z, 0.f);
        pre.w = fmaxf(pre.w + b.w, 0.f);
    }
    if (MODE == 0) {
        // 16x16 GEMM via intra-warp shuffles
        int lane = threadIdx.x & 31;
        int base = lane & ~3;
        float4 y = make_float4(0.f, 0.f, 0.f, 0.f);
        #pragma unroll
        for (int k = 0; k < HID; k++) {
            float hsrc = (k & 3) == 0 ? pre.x : (k & 3) == 1 ? pre.y
                       : (k & 3) == 2 ? pre.z : pre.w;
            float hk = __shfl_sync(0xffffffffu, hsrc, base | (k >> 2));
            float4 wk = Ws4[k * 4 + q];
            y.x = fmaf(hk, wk.x, y.x);
            y.y = fmaf(hk, wk.y, y.y);
            y.z = fmaf(hk, wk.z, y.z);
            y.w = fmaf(hk, wk.w, y.w);
        }
        outv = make_float4(y.x * s, y.y * s, y.z * s, y.w * s);
    } else if (MODE == 1) {
        outv = make_float4(pre.x * s, pre.y * s, pre.z * s, pre.w * s);
    } else {
        outv = pre;
    }
    if (valid) ((float4*)(dstbuf + (long)n * HID))[q] = outv;
}

// ---- GEMM3: out = g_a @ W3 + b3  [100k,16]x[16,500] ------------------------
__global__ void __launch_bounds__(128) k_gemm3(const float* __restrict__ W3,
                                               const float* __restrict__ b3,
                                               float* __restrict__ out) {
    __shared__ float4 as4[64 * 4];
    int tid = threadIdx.x;
    int r0  = blockIdx.x * 64;
    int nrows = N_NODES - r0; if (nrows > 64) nrows = 64;

    const float4* av = (const float4*)(g_a + (long)r0 * HID);
    for (int i = tid; i < nrows * 4; i += 128) as4[i] = av[i];
    __syncthreads();

    if (tid >= 125) return;
    int c = tid * 4;

    unsigned long long w[32];
    #pragma unroll
    for (int k = 0; k < HID; k++) {
        float4 wv = *(const float4*)(W3 + k * OUT_DIM + c);
        w[k*2+0] = pack2(wv.x, wv.y);
        w[k*2+1] = pack2(wv.z, wv.w);
    }
    float4 bb = *(const float4*)(b3 + c);
    unsigned long long b01 = pack2(bb.x, bb.y), b23 = pack2(bb.z, bb.w);

    for (int r = 0; r < nrows; r++) {
        unsigned long long acc0 = b01, acc1 = b23;
        #pragma unroll
        for (int k4 = 0; k4 < 4; k4++) {
            float4 a = as4[r * 4 + k4];
            int kb = k4 * 4;
            { unsigned long long ap = pack2(a.x); fma2(acc0, ap, w[(kb+0)*2]); fma2(acc1, ap, w[(kb+0)*2+1]); }
            { unsigned long long ap = pack2(a.y); fma2(acc0, ap, w[(kb+1)*2]); fma2(acc1, ap, w[(kb+1)*2+1]); }
            { unsigned long long ap = pack2(a.z); fma2(acc0, ap, w[(kb+2)*2]); fma2(acc1, ap, w[(kb+2)*2+1]); }
            { unsigned long long ap = pack2(a.w); fma2(acc0, ap, w[(kb+3)*2]); fma2(acc1, ap, w[(kb+3)*2+1]); }
        }
        float2 lo = unpack2(acc0), hi = unpack2(acc1);
        *(float4*)(out + (long)(r0 + r) * OUT_DIM + c) = make_float4(lo.x, lo.y, hi.x, hi.y);
    }
}

// ---------------- launch ----------------------------------------------------
extern "C" void kernel_launch(void* const* d_in, const int* in_sizes, int n_in,
                              void* d_out, int out_size) {
    const float* x   = (const float*)d_in[0];
    const int*   ei  = (const int*)  d_in[1];
    const float* W1  = (const float*)d_in[2];
    const float* b1  = (const float*)d_in[3];
    const float* W2  = (const float*)d_in[4];
    const float* b2  = (const float*)d_in[5];
    const float* W3  = (const float*)d_in[6];
    const float* b3  = (const float*)d_in[7];
    float* out = (float*)d_out;

    const int* src = ei;
    const int* dst = ei + N_EDGES;

    static cudaStream_t s2 = 0;
    static cudaEvent_t evF = 0, evJ = 0;
    static int init_ok = -1;
    if (init_ok < 0) {
        init_ok = 1;
        if (cudaStreamCreateWithFlags(&s2, cudaStreamNonBlocking) != cudaSuccess) init_ok = 0;
        if (init_ok && cudaEventCreateWithFlags(&evF, cudaEventDisableTiming) != cudaSuccess) init_ok = 0;
        if (init_ok && cudaEventCreateWithFlags(&evJ, cudaEventDisableTiming) != cudaSuccess) init_ok = 0;
    }

    const int TB = 256;
    const int gN   = (N_NODES + TB - 1) / TB;              // 391
    const int gE   = (N_EDGES + TB - 1) / TB;              // 12500
    const int gG1  = (N_NODES + 255) / 256;                // 391
    const int gA   = (N_NODES * 4 + TB - 1) / TB;          // 1563
    const int g64  = (N_NODES + 63) / 64;                  // 1563

    cudaStream_t sb = init_ok ? s2 : (cudaStream_t)0;

    if (init_ok) {
        cudaEventRecord(evF, 0);
        cudaStreamWaitEvent(s2, evF, 0);
    }

    // Branch B: CSR build + normalization
    k_reset_cnt<<<gN, TB, 0, sb>>>();
    k_count<<<gE, TB, 0, sb>>>(dst);
    k_scan1<<<NB_SCAN, 256, 0, sb>>>();
    k_scan2<<<1, 128, 0, sb>>>();
    k_scan3<<<gN, TB, 0, sb>>>();
    k_fill<<<gE, TB, 0, sb>>>(src, dst);

    // Branch A: dense layer-1 GEMM (unscaled)
    k_gemm1<<<gG1, TB>>>(x, W1);

    if (init_ok) {
        cudaEventRecord(evJ, s2);
        cudaStreamWaitEvent(0, evJ, 0);
    }

    // join: scale layer-1 features
    k_scale<<<gA, TB>>>();

    // layer 1 -> 2: agg + relu+b1 + @W2 + scale   (g_t -> g_a)
    k_agg_fused<0><<<gA, TB>>>(b1, W2);
    // layer 2 -> 3: agg + relu+b2 + scale          (g_a -> g_t)
    k_agg_fused<1><<<gA, TB>>>(b2, nullptr);
    // layer 3: agg + final scale                   (g_t -> g_a)
    k_agg_fused<2><<<gA, TB>>>(nullptr, nullptr);
    // up-projection
    k_gemm3<<<g64, 128>>>(W3, b3, out);
}